// round 16
// baseline (speedup 1.0000x reference)
#include <cuda_runtime.h>

// ---------------------------------------------------------------------------
// DifferentiableRenderer: Gaussian splat weighted-average render.
// out[b,c,y,x] = sum_n w_n*color_n / (sum_n w_n + 1e-8)
// w_n = opacity_n * exp(-0.5*((x-u_n)^2+(y-v_n)^2)/var_n)
//
// R16 (base: R13, the 10.27us best):
//   (1) 3-FMA eval: per gaussian store (a, -2a*u, -2a*v, a(u^2+v^2)+bop);
//       per pixel hoist pp = px^2+py^2; e = fma(a,pp,fma(nau,px,fma(nav,py,c0))).
//       Eval iter: 2 LDS + 3 FMA + MUFU + 4 acc = 10 instr (was 13).
//   (2) SPLIT=6: 768 blocks = 5.2/SM = 41.5 warps/SM, single wave -> issue% up.
//   (3) eval unroll 4.
//   Single kernel; last-arriving block per tile merges via atom.acq_rel.gpu,
//   fixed slice order (deterministic), counter reset for graph replay.
//   Cut at w < 2^-60: per-pixel abs error <= ~7e-7 << 1e-3 budget.
// ---------------------------------------------------------------------------

#define HH 128
#define WW 128
#define HWP (HH * WW)
#define FXC 150.0f
#define FYC 150.0f
#define CXC 64.0f
#define CYC 64.0f
#define EPSC 1e-8f

#define TILE    16
#define TX_N    (WW / TILE)          // 8
#define TY_N    (HH / TILE)          // 8
#define TILES   (TX_N * TY_N)        // 64
#define SPLIT   6                    // gaussian slices per tile
#define TPB     256                  // threads per render block (1 px each)
#define CHUNK   256                  // gaussians prepped+tested per pass
#define EMIN    (-60.0f)             // log2 weight cutoff

#define MAXB    4

// per (b, tile, split, pixel) partial sums {den, r, g, b} -- L2 resident
__device__ float4 g_part[MAXB * TILES * SPLIT * TPB];
// per (b, tile) arrival counters (zero-init; reset by merging block)
__device__ int g_cnt[MAXB * TILES];

__device__ __forceinline__ float ex2f(float x) {
    float y;
    asm("ex2.approx.ftz.f32 %0, %1;" : "=f"(y) : "f"(x));
    return y;
}
__device__ __forceinline__ float lg2f(float x) {
    float y;
    asm("lg2.approx.ftz.f32 %0, %1;" : "=f"(y) : "f"(x));
    return y;
}
// fetch-add with acq_rel at gpu scope: releases our prior stores, acquires
// peers' released stores. No MEMBAR drain.
__device__ __forceinline__ int atom_add_acqrel(int* p, int v) {
    int old;
    asm volatile("atom.add.acq_rel.gpu.global.s32 %0, [%1], %2;"
                 : "=r"(old) : "l"(p), "r"(v) : "memory");
    return old;
}

// ---------------------------------------------------------------------------
// blockIdx.x = ((b*TILES + tile)*SPLIT + s). 256 threads = one 16x16 tile.
// ---------------------------------------------------------------------------
__global__ void __launch_bounds__(TPB)
render_tiles(float* __restrict__ out,
             const float* __restrict__ pos,
             const float* __restrict__ col,
             const float* __restrict__ opac,
             const float* __restrict__ scal,
             const float* __restrict__ qv,
             const float* __restrict__ tv,
             int N) {
    __shared__ float4 sga[CHUNK];      // a, -2a*u, -2a*v, a(u^2+v^2)+bop
    __shared__ float4 sgb[CHUNK];      // cr, cg, cb, -
    __shared__ int s_wbase[TPB / 32];
    __shared__ int s_wcnt[TPB / 32];
    __shared__ int s_total;
    __shared__ int s_arrival;

    const int tid  = threadIdx.x;
    const int bid  = blockIdx.x;
    const int s    = bid % SPLIT;
    const int m    = bid / SPLIT;                 // b*TILES + tile
    const int tile = m & (TILES - 1);
    const int b    = m / TILES;

    const int tx = tile & (TX_N - 1);
    const int ty = tile / TX_N;
    const float pxf = (float)(tx * TILE + (tid & (TILE - 1)));
    const float pyf = (float)(ty * TILE + (tid / TILE));
    const float pp  = pxf * pxf + pyf * pyf;       // hoisted per pixel
    const float tcx = (float)(tx * TILE) + 7.5f;   // tile center
    const float tcy = (float)(ty * TILE) + 7.5f;

    // --- per-batch camera, hoisted (broadcast loads, L1 hits) ---
    float qw = qv[b * 4 + 0], qx = qv[b * 4 + 1];
    float qy = qv[b * 4 + 2], qz = qv[b * 4 + 3];
    {
        float inv = rsqrtf(qw * qw + qx * qx + qy * qy + qz * qz);
        qw *= inv; qx *= inv; qy *= inv; qz *= inv;
    }
    const float R00 = 1.0f - 2.0f * (qy * qy + qz * qz);
    const float R01 = 2.0f * (qx * qy - qz * qw);
    const float R02 = 2.0f * (qx * qz + qy * qw);
    const float R10 = 2.0f * (qx * qy + qz * qw);
    const float R11 = 1.0f - 2.0f * (qx * qx + qz * qz);
    const float R12 = 2.0f * (qy * qz - qx * qw);
    const float R20 = 2.0f * (qx * qz - qy * qw);
    const float R21 = 2.0f * (qy * qz + qx * qw);
    const float R22 = 1.0f - 2.0f * (qx * qx + qy * qy);
    const float t0 = tv[b * 3 + 0], t1 = tv[b * 3 + 1], t2 = tv[b * 3 + 2];

    const int lo = (s * N) / SPLIT;
    const int hi = ((s + 1) * N) / SPLIT;

    const int wid  = tid >> 5;
    const int lane = tid & 31;
    const unsigned lanemask_lt = (1u << lane) - 1u;

    float den = 0.f, ar = 0.f, ag = 0.f, ab = 0.f;

    for (int cb = lo; cb < hi; cb += CHUNK) {
        // --- prep + cull one gaussian per thread ---
        const int j = cb + tid;                    // gaussian index
        bool keep = false;
        float4 ga;
        if (j < hi) {
            const float px = pos[j * 3 + 0];
            const float py = pos[j * 3 + 1];
            const float pz = pos[j * 3 + 2];
            const float cxm = R00 * px + R01 * py + R02 * pz + t0;
            const float cym = R10 * px + R11 * py + R12 * pz + t1;
            const float czm = R20 * px + R21 * py + R22 * pz + t2;
            const float invz = __fdividef(1.0f, czm);
            const float u = cxm * invz * FXC + CXC;
            const float v = cym * invz * FYC + CYC;
            const float sc = scal[j];
            // a = -0.5 * log2(e) / var
            const float a = __fdividef(-0.72134752044448170f, sc * sc);
            const float bop = lg2f(opac[j]);       // opac=0 -> -inf -> culled

            float dx = fmaxf(fabsf(u - tcx) - 7.5f, 0.0f);
            float dy = fmaxf(fabsf(v - tcy) - 7.5f, 0.0f);
            float mind2 = dx * dx + dy * dy;
            float emax  = fmaf(a, mind2, bop);     // a*mind2 + bop (a<0)
            keep = (emax >= EMIN);

            if (keep) {
                // fold into 3-FMA-per-pixel form
                const float nau = -2.0f * a * u;
                const float nav = -2.0f * a * v;
                const float c0  = fmaf(a, u * u + v * v, bop);
                ga = make_float4(a, nau, nav, c0);
            }
        }

        // --- stable compaction (gaussian-index order preserved) ---
        const unsigned mask = __ballot_sync(0xffffffffu, keep);
        if (lane == 0) s_wcnt[wid] = __popc(mask);
        __syncthreads();
        if (tid == 0) {
            int acc = 0;
            #pragma unroll
            for (int w = 0; w < TPB / 32; w++) { s_wbase[w] = acc; acc += s_wcnt[w]; }
            s_total = acc;
        }
        __syncthreads();
        if (keep) {
            const int posn = s_wbase[wid] + __popc(mask & lanemask_lt);
            sga[posn] = ga;
            sgb[posn] = make_float4(col[j * 3 + 0], col[j * 3 + 1],
                                    col[j * 3 + 2], 0.0f);
        }
        __syncthreads();

        // --- evaluate survivors against this thread's pixel (3 FMA + ex2) ---
        const int cnt = s_total;
        #pragma unroll 4
        for (int t = 0; t < cnt; t++) {
            const float4 A  = sga[t];              // a, nau, nav, c0 (broadcast)
            const float4 Cc = sgb[t];
            const float e = fmaf(A.x, pp, fmaf(A.y, pxf, fmaf(A.z, pyf, A.w)));
            const float w = ex2f(e);
            den += w;
            ar = fmaf(w, Cc.x, ar);
            ag = fmaf(w, Cc.y, ag);
            ab = fmaf(w, Cc.z, ab);
        }
        __syncthreads();
    }

    // --- publish this slice's partial to L2 ---
    __stcg(&g_part[bid * TPB + tid], make_float4(den, ar, ag, ab));
    __syncthreads();   // intra-block HB: all stores precede tid0's release

    // --- last-arriving block of this tile merges ---
    if (tid == 0) s_arrival = atom_add_acqrel(&g_cnt[m], 1);
    __syncthreads();   // acquire by tid0 + barrier -> HB for all readers

    if (s_arrival == SPLIT - 1) {
        // all SPLIT partials for tile m visible in L2 (release/acquire chain)
        // fixed slice order -> deterministic regardless of merger identity
        float4 acc = make_float4(0.f, 0.f, 0.f, 0.f);
        #pragma unroll
        for (int sl = 0; sl < SPLIT; sl++) {
            const float4 p = __ldcg(&g_part[(m * SPLIT + sl) * TPB + tid]);
            acc.x += p.x; acc.y += p.y; acc.z += p.z; acc.w += p.w;
        }

        const float invd = __fdividef(1.0f, acc.x + EPSC);

        const int px = tx * TILE + (tid & (TILE - 1));
        const int py = ty * TILE + (tid / TILE);
        float* ob = out + (size_t)b * 3 * HWP + py * WW + px;
        ob[0]       = acc.y * invd;   // R plane
        ob[HWP]     = acc.z * invd;   // G plane
        ob[2 * HWP] = acc.w * invd;   // B plane

        if (tid == 0) g_cnt[m] = 0;   // reset for next launch / graph replay
    }
}

// ---------------------------------------------------------------------------
extern "C" void kernel_launch(void* const* d_in, const int* in_sizes, int n_in,
                              void* d_out, int out_size) {
    const float* positions = (const float*)d_in[0];
    const float* colors    = (const float*)d_in[1];
    const float* opacities = (const float*)d_in[2];
    const float* scales    = (const float*)d_in[3];
    const float* qvec      = (const float*)d_in[4];
    const float* tvec      = (const float*)d_in[5];
    float* out = (float*)d_out;

    const int N = in_sizes[0] / 3;
    const int B = in_sizes[4] / 4;

    render_tiles<<<B * TILES * SPLIT, TPB>>>(out, positions, colors, opacities,
                                             scales, qvec, tvec, N);
}

// round 17
// speedup vs baseline: 1.1416x; 1.1416x over previous
#include <cuda_runtime.h>

// ---------------------------------------------------------------------------
// DifferentiableRenderer: Gaussian splat weighted-average render.
// out[b,c,y,x] = sum_n w_n*color_n / (sum_n w_n + 1e-8)
// w_n = opacity_n * exp(-0.5*((x-u_n)^2+(y-v_n)^2)/var_n)
//
// R17 = R13 (best known: SPLIT=4, TPB=256, scalar eval, fused acq_rel merge)
//   with ONE change: CHUNK 256->512. Each thread preps+culls TWO gaussians
//   per pass (sub-chunks [cb,cb+256) and [cb+256,cb+512)), halving the
//   per-pass fixed overhead (barriers, loop carry) that R16's post-mortem
//   identified as rivaling the eval work. Compaction stays stable: scatter
//   sub-chunk 0 survivors then sub-chunk 1 -> global index order preserved.
//   Cut at w < 2^-60: per-pixel abs error <= ~7e-7 << 1e-3 budget.
// ---------------------------------------------------------------------------

#define HH 128
#define WW 128
#define HWP (HH * WW)
#define FXC 150.0f
#define FYC 150.0f
#define CXC 64.0f
#define CYC 64.0f
#define EPSC 1e-8f

#define TILE    16
#define TX_N    (WW / TILE)          // 8
#define TY_N    (HH / TILE)          // 8
#define TILES   (TX_N * TY_N)        // 64
#define SPLIT   4                    // gaussian slices per tile
#define TPB     256                  // threads per render block (1 px each)
#define CHUNK   512                  // gaussians prepped+tested per pass (2/thread)
#define EMIN    (-60.0f)             // log2 weight cutoff

#define MAXB    4
#define NW      (TPB / 32)           // 8 warps

// per (b, tile, split, pixel) partial sums {den, r, g, b} -- L2 resident
__device__ float4 g_part[MAXB * TILES * SPLIT * TPB];
// per (b, tile) arrival counters (zero-init; reset by merging block)
__device__ int g_cnt[MAXB * TILES];

__device__ __forceinline__ float ex2f(float x) {
    float y;
    asm("ex2.approx.ftz.f32 %0, %1;" : "=f"(y) : "f"(x));
    return y;
}
__device__ __forceinline__ float lg2f(float x) {
    float y;
    asm("lg2.approx.ftz.f32 %0, %1;" : "=f"(y) : "f"(x));
    return y;
}
// fetch-add with acq_rel at gpu scope: releases our prior stores, acquires
// peers' released stores. No MEMBAR drain.
__device__ __forceinline__ int atom_add_acqrel(int* p, int v) {
    int old;
    asm volatile("atom.add.acq_rel.gpu.global.s32 %0, [%1], %2;"
                 : "=r"(old) : "l"(p), "r"(v) : "memory");
    return old;
}

// ---------------------------------------------------------------------------
// blockIdx.x = ((b*TILES + tile)*SPLIT + s). 256 threads = one 16x16 tile.
// ---------------------------------------------------------------------------
__global__ void __launch_bounds__(TPB)
render_tiles(float* __restrict__ out,
             const float* __restrict__ pos,
             const float* __restrict__ col,
             const float* __restrict__ opac,
             const float* __restrict__ scal,
             const float* __restrict__ qv,
             const float* __restrict__ tv,
             int N) {
    __shared__ float4 sga[CHUNK];      // u, v, a, bop
    __shared__ float4 sgb[CHUNK];      // cr, cg, cb, -
    __shared__ int s_wcnt[2 * NW];     // per-warp survivor counts, 2 sub-chunks
    __shared__ int s_wbase[2 * NW];
    __shared__ int s_total;
    __shared__ int s_arrival;

    const int tid  = threadIdx.x;
    const int bid  = blockIdx.x;
    const int s    = bid & (SPLIT - 1);
    const int m    = bid / SPLIT;                 // b*TILES + tile
    const int tile = m & (TILES - 1);
    const int b    = m / TILES;

    const int tx = tile & (TX_N - 1);
    const int ty = tile / TX_N;
    const float pxf = (float)(tx * TILE + (tid & (TILE - 1)));
    const float pyf = (float)(ty * TILE + (tid / TILE));
    const float tcx = (float)(tx * TILE) + 7.5f;   // tile center
    const float tcy = (float)(ty * TILE) + 7.5f;

    // --- per-batch camera, hoisted (broadcast loads, L1 hits) ---
    float qw = qv[b * 4 + 0], qx = qv[b * 4 + 1];
    float qy = qv[b * 4 + 2], qz = qv[b * 4 + 3];
    {
        float inv = rsqrtf(qw * qw + qx * qx + qy * qy + qz * qz);
        qw *= inv; qx *= inv; qy *= inv; qz *= inv;
    }
    const float R00 = 1.0f - 2.0f * (qy * qy + qz * qz);
    const float R01 = 2.0f * (qx * qy - qz * qw);
    const float R02 = 2.0f * (qx * qz + qy * qw);
    const float R10 = 2.0f * (qx * qy + qz * qw);
    const float R11 = 1.0f - 2.0f * (qx * qx + qz * qz);
    const float R12 = 2.0f * (qy * qz - qx * qw);
    const float R20 = 2.0f * (qx * qz - qy * qw);
    const float R21 = 2.0f * (qy * qz + qx * qw);
    const float R22 = 1.0f - 2.0f * (qx * qx + qy * qy);
    const float t0 = tv[b * 3 + 0], t1 = tv[b * 3 + 1], t2 = tv[b * 3 + 2];

    const int lo = (s * N) / SPLIT;
    const int hi = ((s + 1) * N) / SPLIT;

    const int wid  = tid >> 5;
    const int lane = tid & 31;
    const unsigned lanemask_lt = (1u << lane) - 1u;

    float den = 0.f, ar = 0.f, ag = 0.f, ab = 0.f;

    for (int cb = lo; cb < hi; cb += CHUNK) {
        // --- prep + cull TWO gaussians per thread (independent -> MLP) ---
        const int j0 = cb + tid;
        const int j1 = cb + TPB + tid;
        bool keep0 = false, keep1 = false;
        float4 ga0, ga1;

        if (j0 < hi) {
            const float px = pos[j0 * 3 + 0];
            const float py = pos[j0 * 3 + 1];
            const float pz = pos[j0 * 3 + 2];
            const float cxm = R00 * px + R01 * py + R02 * pz + t0;
            const float cym = R10 * px + R11 * py + R12 * pz + t1;
            const float czm = R20 * px + R21 * py + R22 * pz + t2;
            const float invz = __fdividef(1.0f, czm);
            const float u = cxm * invz * FXC + CXC;
            const float v = cym * invz * FYC + CYC;
            const float sc = scal[j0];
            const float a = __fdividef(-0.72134752044448170f, sc * sc);
            const float bop = lg2f(opac[j0]);      // opac=0 -> -inf -> culled
            ga0 = make_float4(u, v, a, bop);
            float dx = fmaxf(fabsf(u - tcx) - 7.5f, 0.0f);
            float dy = fmaxf(fabsf(v - tcy) - 7.5f, 0.0f);
            keep0 = (fmaf(a, dx * dx + dy * dy, bop) >= EMIN);
        }
        if (j1 < hi) {
            const float px = pos[j1 * 3 + 0];
            const float py = pos[j1 * 3 + 1];
            const float pz = pos[j1 * 3 + 2];
            const float cxm = R00 * px + R01 * py + R02 * pz + t0;
            const float cym = R10 * px + R11 * py + R12 * pz + t1;
            const float czm = R20 * px + R21 * py + R22 * pz + t2;
            const float invz = __fdividef(1.0f, czm);
            const float u = cxm * invz * FXC + CXC;
            const float v = cym * invz * FYC + CYC;
            const float sc = scal[j1];
            const float a = __fdividef(-0.72134752044448170f, sc * sc);
            const float bop = lg2f(opac[j1]);
            ga1 = make_float4(u, v, a, bop);
            float dx = fmaxf(fabsf(u - tcx) - 7.5f, 0.0f);
            float dy = fmaxf(fabsf(v - tcy) - 7.5f, 0.0f);
            keep1 = (fmaf(a, dx * dx + dy * dy, bop) >= EMIN);
        }

        // --- stable compaction: sub-chunk 0 then sub-chunk 1 (index order) ---
        const unsigned mask0 = __ballot_sync(0xffffffffu, keep0);
        const unsigned mask1 = __ballot_sync(0xffffffffu, keep1);
        if (lane == 0) {
            s_wcnt[wid]      = __popc(mask0);
            s_wcnt[NW + wid] = __popc(mask1);
        }
        __syncthreads();
        if (tid == 0) {
            int acc = 0;
            #pragma unroll
            for (int w = 0; w < 2 * NW; w++) { s_wbase[w] = acc; acc += s_wcnt[w]; }
            s_total = acc;
        }
        __syncthreads();
        if (keep0) {
            const int posn = s_wbase[wid] + __popc(mask0 & lanemask_lt);
            sga[posn] = ga0;
            sgb[posn] = make_float4(col[j0 * 3 + 0], col[j0 * 3 + 1],
                                    col[j0 * 3 + 2], 0.0f);
        }
        if (keep1) {
            const int posn = s_wbase[NW + wid] + __popc(mask1 & lanemask_lt);
            sga[posn] = ga1;
            sgb[posn] = make_float4(col[j1 * 3 + 0], col[j1 * 3 + 1],
                                    col[j1 * 3 + 2], 0.0f);
        }
        __syncthreads();

        // --- evaluate survivors against this thread's pixel ---
        const int cnt = s_total;
        #pragma unroll 2
        for (int t = 0; t < cnt; t++) {
            const float4 A  = sga[t];              // u, v, a, bop (broadcast)
            const float4 Cc = sgb[t];
            const float dv = pyf - A.y;
            const float c2 = fmaf(A.z * dv, dv, A.w);
            const float du = pxf - A.x;
            const float e  = fmaf(A.z * du, du, c2);
            const float w  = ex2f(e);
            den += w;
            ar = fmaf(w, Cc.x, ar);
            ag = fmaf(w, Cc.y, ag);
            ab = fmaf(w, Cc.z, ab);
        }
        __syncthreads();
    }

    // --- publish this slice's partial to L2 ---
    __stcg(&g_part[bid * TPB + tid], make_float4(den, ar, ag, ab));
    __syncthreads();   // intra-block HB: all stores precede tid0's release

    // --- last-arriving block of this tile merges ---
    if (tid == 0) s_arrival = atom_add_acqrel(&g_cnt[m], 1);
    __syncthreads();   // acquire by tid0 + barrier -> HB for all readers

    if (s_arrival == SPLIT - 1) {
        // all SPLIT partials for tile m visible in L2 (release/acquire chain)
        // fixed slice order -> deterministic regardless of merger identity
        const float4 p0 = __ldcg(&g_part[(m * SPLIT + 0) * TPB + tid]);
        const float4 p1 = __ldcg(&g_part[(m * SPLIT + 1) * TPB + tid]);
        const float4 p2 = __ldcg(&g_part[(m * SPLIT + 2) * TPB + tid]);
        const float4 p3 = __ldcg(&g_part[(m * SPLIT + 3) * TPB + tid]);

        float4 acc;
        acc.x = (p0.x + p1.x) + (p2.x + p3.x);
        acc.y = (p0.y + p1.y) + (p2.y + p3.y);
        acc.z = (p0.z + p1.z) + (p2.z + p3.z);
        acc.w = (p0.w + p1.w) + (p2.w + p3.w);

        const float invd = __fdividef(1.0f, acc.x + EPSC);

        const int px = tx * TILE + (tid & (TILE - 1));
        const int py = ty * TILE + (tid / TILE);
        float* ob = out + (size_t)b * 3 * HWP + py * WW + px;
        ob[0]       = acc.y * invd;   // R plane
        ob[HWP]     = acc.z * invd;   // G plane
        ob[2 * HWP] = acc.w * invd;   // B plane

        if (tid == 0) g_cnt[m] = 0;   // reset for next launch / graph replay
    }
}

// ---------------------------------------------------------------------------
extern "C" void kernel_launch(void* const* d_in, const int* in_sizes, int n_in,
                              void* d_out, int out_size) {
    const float* positions = (const float*)d_in[0];
    const float* colors    = (const float*)d_in[1];
    const float* opacities = (const float*)d_in[2];
    const float* scales    = (const float*)d_in[3];
    const float* qvec      = (const float*)d_in[4];
    const float* tvec      = (const float*)d_in[5];
    float* out = (float*)d_out;

    const int N = in_sizes[0] / 3;
    const int B = in_sizes[4] / 4;

    render_tiles<<<B * TILES * SPLIT, TPB>>>(out, positions, colors, opacities,
                                             scales, qvec, tvec, N);
}